// round 8
// baseline (speedup 1.0000x reference)
#include <cuda_runtime.h>
#include <math.h>

#define FULLMASK 0xffffffffu

#define BB   2
#define NN   2048
#define HH   8
#define HID  128
#define VD   16
#define BN   (BB * NN)
// locality=5 -> pos=0.05*2047=102.35 -> need 103rd smallest (0-indexed 102)
#define KTH  103

// GEMM smem: Ws [128][64] f32 (32KB) + As [32][128] f32 (16KB) = 48KB
#define GEMM_SMEM (32768 + 16384)
// Attention smem: full v, 2048 rows x stride-18 f32 = 144KB
#define ATTN_SMEM (NN * 18 * 4)

typedef unsigned long long ull;

// ---------------- scratch (device globals; no allocation) ----------------
__device__ float  g_en[BN * HID];
__device__ float  g_x [BN * HID];
__device__ float  g_h [BN * HID];
__device__ float  g_t [BN * HID];
__device__ float  g_r [BN * HID];
__device__ float  g_v [BN * HID];
__device__ float2 g_rowstats[BN];

// ---------------- f32x2 packed helpers ----------------
__device__ __forceinline__ ull pack2(float x, float y) {
    ull r;
    asm("mov.b64 %0, {%1, %2};" : "=l"(r) : "r"(__float_as_uint(x)), "r"(__float_as_uint(y)));
    return r;
}
__device__ __forceinline__ void unpack2(ull u, float& x, float& y) {
    unsigned a, b;
    asm("mov.b64 {%0, %1}, %2;" : "=r"(a), "=r"(b) : "l"(u));
    x = __uint_as_float(a); y = __uint_as_float(b);
}
__device__ __forceinline__ ull fma2(ull a, ull b, ull c) {
    ull d;
    asm("fma.rn.f32x2 %0, %1, %2, %3;" : "=l"(d) : "l"(a), "l"(b), "l"(c));
    return d;
}
__device__ __forceinline__ ull add2(ull a, ull b) {
    ull d;
    asm("add.rn.f32x2 %0, %1, %2;" : "=l"(d) : "l"(a), "l"(b));
    return d;
}
__device__ __forceinline__ float ex2f(float x) {
    float r;
    asm("ex2.approx.f32 %0, %1;" : "=f"(r) : "f"(x));
    return r;
}

__device__ __forceinline__ float gelu_f(float x) {
    // exact (erf) gelu, matching jax.nn.gelu(approximate=False)
    return 0.5f * x * (1.0f + erff(x * 0.70710678118654752f));
}

// ---------------- per-row order statistics of m_dist ----------------
__global__ void rowstats_kernel(const float* __restrict__ md, float2* __restrict__ rs) {
    int warp = threadIdx.x >> 5, lane = threadIdx.x & 31;
    int row = blockIdx.x * 8 + warp;
    const float* p = md + (size_t)row * NN + lane;
    unsigned mu[64];
    float mn = 1e30f;
#pragma unroll
    for (int i = 0; i < 64; ++i) {
        float x = p[i * 32];
        mn = fminf(mn, x);
        mu[i] = __float_as_uint(x);
    }
#pragma unroll
    for (int off = 16; off; off >>= 1)
        mn = fminf(mn, __shfl_xor_sync(FULLMASK, mn, off));

    unsigned lo = 0u, hi = 0x3F800000u;  // bit patterns of [0,1)
    while (hi - lo > 1u) {
        unsigned mid = (lo + hi) >> 1;
        int c = 0;
#pragma unroll
        for (int i = 0; i < 64; ++i) c += (mu[i] <= mid) ? 1 : 0;
        c = __reduce_add_sync(FULLMASK, c);
        if (c >= KTH) hi = mid; else lo = mid;
    }
    if (lane == 0) rs[row] = make_float2(mn, __uint_as_float(hi));
}

// ---------------- encoder: gelu(inputs @ en_W + en_b), K=3 ----------------
__global__ void enc_kernel(const float* __restrict__ inp, const float* __restrict__ W,
                           const float* __restrict__ bvec, float* __restrict__ out) {
    int token = blockIdx.x, c = threadIdx.x;
    float x0 = inp[token * 3 + 0];
    float x1 = inp[token * 3 + 1];
    float x2 = inp[token * 3 + 2];
    float s = bvec[c];
    s = fmaf(x0, W[c], s);
    s = fmaf(x1, W[HID + c], s);
    s = fmaf(x2, W[2 * HID + c], s);
    out[(size_t)token * HID + c] = gelu_f(s);
}

// ---------------- GEMM body: 32 rows x 64 cols per CTA ----------------
// vproj: W is head-major (H, HID, VD); logical col c maps to
// W[(c>>4)*HID*VD + k*VD + (c&15)] — 4 consecutive cols stay contiguous.
__device__ __forceinline__ void gemm3_body(
    const float* __restrict__ A, const float* __restrict__ W,
    const float* __restrict__ bias, const float* __restrict__ res,
    float* __restrict__ out, int act, int vproj, float* sm)
{
    float* Ws = sm;              // [128][64]
    float* As = sm + 128 * 64;   // [32][128]

    int tid = threadIdx.x, lane = tid & 31, warp = tid >> 5;
    int row0 = blockIdx.x * 32;
    int cbase = blockIdx.y * 64;

    if (vproj) {
#pragma unroll
        for (int idx = tid; idx < 128 * 16; idx += 256) {
            int k = idx >> 4, q = idx & 15;
            int c0 = cbase + q * 4;
            const float* src = W + (size_t)(c0 >> 4) * (HID * VD) + k * VD + (c0 & 15);
            *(float4*)(Ws + k * 64 + q * 4) = *(const float4*)src;
        }
    } else {
#pragma unroll
        for (int idx = tid; idx < 128 * 16; idx += 256) {
            int k = idx >> 4, q = idx & 15;
            *(float4*)(Ws + k * 64 + q * 4) = *(const float4*)(W + (size_t)k * HID + cbase + q * 4);
        }
    }
#pragma unroll
    for (int idx = tid; idx < 32 * 32; idx += 256) {
        int r = idx >> 5, q = idx & 31;
        *(float4*)(As + r * HID + q * 4) = *(const float4*)(A + (size_t)(row0 + r) * HID + q * 4);
    }
    __syncthreads();

    ull acc[4] = {0ull, 0ull, 0ull, 0ull};
    const ull* Wu = (const ull*)Ws;          // [k][32]
    const float* a0 = As + warp * 4 * HID;

#pragma unroll 8
    for (int k = 0; k < HID; ++k) {
        ull wp = Wu[k * 32 + lane];
        float x0 = a0[0 * HID + k];
        float x1 = a0[1 * HID + k];
        float x2 = a0[2 * HID + k];
        float x3 = a0[3 * HID + k];
        acc[0] = fma2(pack2(x0, x0), wp, acc[0]);
        acc[1] = fma2(pack2(x1, x1), wp, acc[1]);
        acc[2] = fma2(pack2(x2, x2), wp, acc[2]);
        acc[3] = fma2(pack2(x3, x3), wp, acc[3]);
    }

    float b0 = 0.f, b1 = 0.f;
    if (bias) {
        float2 bv = *(const float2*)(bias + cbase + 2 * lane);
        b0 = bv.x; b1 = bv.y;
    }
#pragma unroll
    for (int i = 0; i < 4; ++i) {
        int row = row0 + warp * 4 + i;
        float o0, o1;
        unpack2(acc[i], o0, o1);
        o0 += b0; o1 += b1;
        if (res) {
            float2 rv = *(const float2*)(res + (size_t)row * HID + cbase + 2 * lane);
            o0 += rv.x; o1 += rv.y;
        }
        if (act) { o0 = gelu_f(o0); o1 = gelu_f(o1); }
        *(float2*)(out + (size_t)row * HID + cbase + 2 * lane) = make_float2(o0, o1);
    }
}

__global__ void __launch_bounds__(256) gemm3_kernel(
    const float* __restrict__ A, const float* __restrict__ W,
    const float* __restrict__ bias, const float* __restrict__ res,
    float* __restrict__ out, int act)
{
    extern __shared__ float sm[];
    gemm3_body(A, W, bias, res, out, act, 0, sm);
}

// paired GEMM on the same A. z=0: v-proj from head-major Whead (no bias).
// z=1: skip-proj out1 = A@W1 + b1.
__global__ void __launch_bounds__(256) gemm3p_kernel(
    const float* __restrict__ A,
    const float* __restrict__ Whead, float* __restrict__ out0,
    const float* __restrict__ W1, const float* __restrict__ b1,
    float* __restrict__ out1)
{
    extern __shared__ float sm[];
    if (blockIdx.z == 0) gemm3_body(A, Whead, nullptr, nullptr, out0, 0, 1, sm);
    else                 gemm3_body(A, W1,    b1,      nullptr, out1, 0, 0, sm);
}

// ---------------- fused percentile-softmax attention + gelu ----------------
// CTA: 512 threads = 16 warps x 4 rows = 64 rows, one (b,h). Full v (2048x16)
// in smem, stride 18 (conflict-free LDS.64). Lane <-> j. Depth-4 prefetch
// ring on m_dist (distance ~4 steps ≈ 600cyc > 262cyc L2). exp once per
// (i,j); 16 dims as 8 packed f32x2 FMAs; v bytes amortized over 4 rows.
template <int MASKED>
__global__ void __launch_bounds__(512, 1) attn7_kernel(
    const float* __restrict__ md, const float* __restrict__ v,
    const float* __restrict__ rvec, const float2* __restrict__ rs,
    float* __restrict__ out)
{
    extern __shared__ float vs[];   // [2048][18]
    int b = blockIdx.z, h = blockIdx.y;
    float rr = rvec[h];
    float r2 = rr * rr;
    const float L2E = 1.4426950408889634f;
    float nr2l = -r2 * L2E;

    int tid = threadIdx.x;
    int lane = tid & 31, warp = tid >> 5;
    int i0 = blockIdx.x * 64 + warp * 4;

    // stage full v_h into smem
    const float* vg = v + (size_t)b * NN * HID + h * VD;
    for (int idx = tid; idx < NN * 8; idx += 512) {
        int jj = idx >> 3, dd = (idx & 7) << 1;
        float2 val = *(const float2*)(vg + (size_t)jj * HID + dd);
        *(float2*)(vs + jj * 18 + dd) = val;
    }

    float msdl[4], s102[4];
    ull wsA = 0ull, wsB = 0ull;     // packed (w0,w1), (w2,w3) sums
    ull acc[4][8];
#pragma unroll
    for (int g = 0; g < 4; ++g) {
        float2 st = rs[b * NN + i0 + g];
        msdl[g] = (st.x * r2) * L2E;  // st.x*r2 == min_j(sd) exactly (monotone)
        s102[g] = st.y;
#pragma unroll
        for (int d = 0; d < 8; ++d) acc[g][d] = 0ull;
    }

    const float* mrow = md + ((size_t)b * NN + i0) * NN + lane;

    __syncthreads();

    // prime depth-4 m prefetch ring
    float mr[4][4];
#pragma unroll
    for (int d = 0; d < 4; ++d)
#pragma unroll
        for (int g = 0; g < 4; ++g) mr[g][d] = mrow[(size_t)g * NN + 32 * d];

    for (int t = 0; t < NN / 32; ++t) {
        int slot = t & 3;
        int j = lane + 32 * t;

        const ull* vrow = (const ull*)(vs + j * 18);
        ull v0 = vrow[0], v1 = vrow[1], v2 = vrow[2], v3 = vrow[3];
        ull v4 = vrow[4], v5 = vrow[5], v6 = vrow[6], v7 = vrow[7];

        float m0 = mr[0][slot], m1 = mr[1][slot], m2 = mr[2][slot], m3 = mr[3][slot];

        // prefetch m for step t+4 (clamped; redundant tail prefetches unused)
        int tp = t + 4; if (tp > NN / 32 - 1) tp = NN / 32 - 1;
        mr[0][slot] = mrow[0 * (size_t)NN + 32 * tp];
        mr[1][slot] = mrow[1 * (size_t)NN + 32 * tp];
        mr[2][slot] = mrow[2 * (size_t)NN + 32 * tp];
        mr[3][slot] = mrow[3 * (size_t)NN + 32 * tp];

        float e0 = ex2f(fmaf(m0, nr2l, msdl[0]));
        float e1 = ex2f(fmaf(m1, nr2l, msdl[1]));
        float e2 = ex2f(fmaf(m2, nr2l, msdl[2]));
        float e3 = ex2f(fmaf(m3, nr2l, msdl[3]));
        float w0 = MASKED ? ((m0 <= s102[0]) ? e0 : 0.f) : e0;
        float w1 = MASKED ? ((m1 <= s102[1]) ? e1 : 0.f) : e1;
        float w2 = MASKED ? ((m2 <= s102[2]) ? e2 : 0.f) : e2;
        float w3 = MASKED ? ((m3 <= s102[3]) ? e3 : 0.f) : e3;
        wsA = add2(wsA, pack2(w0, w1));
        wsB = add2(wsB, pack2(w2, w3));
        ull wp0 = pack2(w0, w0);
        ull wp1 = pack2(w1, w1);
        ull wp2 = pack2(w2, w2);
        ull wp3 = pack2(w3, w3);

        acc[0][0] = fma2(wp0, v0, acc[0][0]);  acc[0][1] = fma2(wp0, v1, acc[0][1]);
        acc[0][2] = fma2(wp0, v2, acc[0][2]);  acc[0][3] = fma2(wp0, v3, acc[0][3]);
        acc[0][4] = fma2(wp0, v4, acc[0][4]);  acc[0][5] = fma2(wp0, v5, acc[0][5]);
        acc[0][6] = fma2(wp0, v6, acc[0][6]);  acc[0][7] = fma2(wp0, v7, acc[0][7]);

        acc[1][0] = fma2(wp1, v0, acc[1][0]);  acc[1][1] = fma2(wp1, v1, acc[1][1]);
        acc[1][2] = fma2(wp1, v2, acc[1][2]);  acc[1][3] = fma2(wp1, v3, acc[1][3]);
        acc[1][4] = fma2(wp1, v4, acc[1][4]);  acc[1][5] = fma2(wp1, v5, acc[1][5]);
        acc[1][6] = fma2(wp1, v6, acc[1][6]);  acc[1][7] = fma2(wp1, v7, acc[1][7]);

        acc[2][0] = fma2(wp2, v0, acc[2][0]);  acc[2][1] = fma2(wp2, v1, acc[2][1]);
        acc[2][2] = fma2(wp2, v2, acc[2][2]);  acc[2][3] = fma2(wp2, v3, acc[2][3]);
        acc[2][4] = fma2(wp2, v4, acc[2][4]);  acc[2][5] = fma2(wp2, v5, acc[2][5]);
        acc[2][6] = fma2(wp2, v6, acc[2][6]);  acc[2][7] = fma2(wp2, v7, acc[2][7]);

        acc[3][0] = fma2(wp3, v0, acc[3][0]);  acc[3][1] = fma2(wp3, v1, acc[3][1]);
        acc[3][2] = fma2(wp3, v2, acc[3][2]);  acc[3][3] = fma2(wp3, v3, acc[3][3]);
        acc[3][4] = fma2(wp3, v4, acc[3][4]);  acc[3][5] = fma2(wp3, v5, acc[3][5]);
        acc[3][6] = fma2(wp3, v6, acc[3][6]);  acc[3][7] = fma2(wp3, v7, acc[3][7]);
    }

    // butterfly reduce across 32 lanes (j slots)
    float wsum[4];
    unpack2(wsA, wsum[0], wsum[1]);
    unpack2(wsB, wsum[2], wsum[3]);
#pragma unroll
    for (int off = 16; off; off >>= 1) {
#pragma unroll
        for (int g = 0; g < 4; ++g) {
            wsum[g] += __shfl_xor_sync(FULLMASK, wsum[g], off);
#pragma unroll
            for (int d = 0; d < 8; ++d) {
                ull o = __shfl_xor_sync(FULLMASK, acc[g][d], off);
                acc[g][d] = add2(acc[g][d], o);
            }
        }
    }

    if (lane < 4) {
        int g = lane;
        float inv = 1.0f / wsum[g];
        float o[16];
#pragma unroll
        for (int d = 0; d < 8; ++d) unpack2(acc[g][d], o[2 * d], o[2 * d + 1]);
#pragma unroll
        for (int e = 0; e < 16; ++e) o[e] = gelu_f(o[e] * inv);
        float* dst = out + (size_t)(b * NN + i0 + g) * HID + h * VD;
        *(float4*)(dst + 0)  = make_float4(o[0],  o[1],  o[2],  o[3]);
        *(float4*)(dst + 4)  = make_float4(o[4],  o[5],  o[6],  o[7]);
        *(float4*)(dst + 8)  = make_float4(o[8],  o[9],  o[10], o[11]);
        *(float4*)(dst + 12) = make_float4(o[12], o[13], o[14], o[15]);
    }
}

// ---------------- final 128 -> 1 projection ----------------
__global__ void final_kernel(const float* __restrict__ t, const float* __restrict__ W,
                             const float* __restrict__ bvec, float* __restrict__ out) {
    int warp = threadIdx.x >> 5, lane = threadIdx.x & 31;
    int token = blockIdx.x * 8 + warp;
    const float* p = t + (size_t)token * HID;
    float s = 0.f;
#pragma unroll
    for (int i = 0; i < 4; ++i) s = fmaf(p[lane + 32 * i], W[lane + 32 * i], s);
#pragma unroll
    for (int off = 16; off; off >>= 1) s += __shfl_xor_sync(FULLMASK, s, off);
    if (lane == 0) out[token] = s + bvec[0];
}

// ---------------- orchestration ----------------
static float* symf(const void* sym) {
    void* p = nullptr;
    cudaGetSymbolAddress(&p, sym);
    return (float*)p;
}

extern "C" void kernel_launch(void* const* d_in, const int* in_sizes, int n_in,
                              void* d_out, int out_size) {
    const float* md      = (const float*)d_in[0];
    const float* inputs  = (const float*)d_in[1];
    const float* en_W    = (const float*)d_in[2];
    const float* en_b    = (const float*)d_in[3];
    const float* down_r  = (const float*)d_in[4];
    const float* down_w  = (const float*)d_in[5];
    const float* mlp1_W1 = (const float*)d_in[6];
    const float* mlp1_b1 = (const float*)d_in[7];
    const float* mlp1_W2 = (const float*)d_in[8];
    const float* mlp1_b2 = (const float*)d_in[9];
    const float* w1_W    = (const float*)d_in[10];
    const float* w1_b    = (const float*)d_in[11];
    const float* pa_r    = (const float*)d_in[12];
    const float* pa_w    = (const float*)d_in[13];
    const float* blk_W1  = (const float*)d_in[14];
    const float* blk_b1  = (const float*)d_in[15];
    const float* blk_W2  = (const float*)d_in[16];
    const float* blk_b2  = (const float*)d_in[17];
    const float* wi_W    = (const float*)d_in[18];
    const float* wi_b    = (const float*)d_in[19];
    const float* up_r    = (const float*)d_in[20];
    const float* up_w    = (const float*)d_in[21];
    const float* mlp2_W1 = (const float*)d_in[22];
    const float* mlp2_b1 = (const float*)d_in[23];
    const float* mlp2_W2 = (const float*)d_in[24];
    const float* mlp2_b2 = (const float*)d_in[25];
    const float* w2_W    = (const float*)d_in[26];
    const float* w2_b    = (const float*)d_in[27];
    const float* de_W1   = (const float*)d_in[28];
    const float* de_b1   = (const float*)d_in[29];
    const float* de_W2   = (const float*)d_in[30];
    const float* de_b2   = (const float*)d_in[31];
    float* outp = (float*)d_out;

    float*  en = symf(g_en);
    float*  x  = symf(g_x);
    float*  hb = symf(g_h);
    float*  tb = symf(g_t);
    float*  rb = symf(g_r);
    float*  vb = symf(g_v);
    float2* rsp;
    { void* p = nullptr; cudaGetSymbolAddress(&p, g_rowstats); rsp = (float2*)p; }

    cudaFuncSetAttribute(gemm3_kernel,  cudaFuncAttributeMaxDynamicSharedMemorySize, GEMM_SMEM);
    cudaFuncSetAttribute(gemm3p_kernel, cudaFuncAttributeMaxDynamicSharedMemorySize, GEMM_SMEM);
    cudaFuncSetAttribute(attn7_kernel<0>, cudaFuncAttributeMaxDynamicSharedMemorySize, ATTN_SMEM);
    cudaFuncSetAttribute(attn7_kernel<1>, cudaFuncAttributeMaxDynamicSharedMemorySize, ATTN_SMEM);

    dim3 ggrid(BN / 32, 2);
    dim3 pgrid(BN / 32, 2, 2);
    dim3 agrid(NN / 64, HH, BB);

    rowstats_kernel<<<BN / 8, 256>>>(md, rsp);
    enc_kernel<<<BN, HID>>>(inputs, en_W, en_b, en);

    // ---- stage 1 (input en, masked mhpa) ----
    gemm3p_kernel<<<pgrid, 256, GEMM_SMEM>>>(en, down_w, vb, w1_W, w1_b, rb);
    attn7_kernel<1><<<agrid, 512, ATTN_SMEM>>>(md, vb, down_r, rsp, hb);
    gemm3_kernel<<<ggrid, 256, GEMM_SMEM>>>(hb, mlp1_W1, mlp1_b1, nullptr, tb, 1);
    gemm3_kernel<<<ggrid, 256, GEMM_SMEM>>>(tb, mlp1_W2, mlp1_b2, rb, x, 1);

    // ---- 4 unmasked blocks ----
    for (int i = 0; i < 4; ++i) {
        gemm3p_kernel<<<pgrid, 256, GEMM_SMEM>>>(x, pa_w + (size_t)i * HH * HID * VD, vb,
            wi_W + (size_t)i * HID * HID, wi_b + (size_t)i * HID, rb);
        attn7_kernel<0><<<agrid, 512, ATTN_SMEM>>>(md, vb, pa_r + (size_t)i * HH, rsp, hb);
        gemm3_kernel<<<ggrid, 256, GEMM_SMEM>>>(hb, blk_W1 + (size_t)i * HID * HID, blk_b1 + (size_t)i * HID, nullptr, tb, 1);
        gemm3_kernel<<<ggrid, 256, GEMM_SMEM>>>(tb, blk_W2 + (size_t)i * HID * HID, blk_b2 + (size_t)i * HID, rb, x, 1);
    }

    // ---- stage 2 (masked mhpa) ----
    gemm3p_kernel<<<pgrid, 256, GEMM_SMEM>>>(x, up_w, vb, w2_W, w2_b, rb);
    attn7_kernel<1><<<agrid, 512, ATTN_SMEM>>>(md, vb, up_r, rsp, hb);
    gemm3_kernel<<<ggrid, 256, GEMM_SMEM>>>(hb, mlp2_W1, mlp2_b1, nullptr, tb, 1);
    gemm3_kernel<<<ggrid, 256, GEMM_SMEM>>>(tb, mlp2_W2, mlp2_b2, rb, x, 1);   // x = de

    // ---- decoder ----
    gemm3_kernel<<<ggrid, 256, GEMM_SMEM>>>(x, de_W1, de_b1, nullptr, tb, 1);
    final_kernel<<<BN / 8, 256>>>(tb, de_W2, de_b2, outp);
}

// round 9
// speedup vs baseline: 1.1194x; 1.1194x over previous
#include <cuda_runtime.h>
#include <math.h>

#define FULLMASK 0xffffffffu

#define BB   2
#define NN   2048
#define HH   8
#define HID  128
#define VD   16
#define BN   (BB * NN)
// locality=5 -> pos=0.05*2047=102.35 -> need 103rd smallest (0-indexed 102)
#define KTH  103

// GEMM smem: Ws [128][64] f32 (32KB) + As [32][128] f32 (16KB) = 48KB
#define GEMM_SMEM (32768 + 16384)
// Attention smem: HALF of v (1024 rows x stride-18 f32) = 72KB -> 3 CTAs/SM
#define VCHUNK 1024
#define ATTN_SMEM (VCHUNK * 18 * 4)

typedef unsigned long long ull;

// ---------------- scratch (device globals; no allocation) ----------------
__device__ float  g_en[BN * HID];
__device__ float  g_x [BN * HID];
__device__ float  g_h [BN * HID];
__device__ float  g_t [BN * HID];
__device__ float  g_r [BN * HID];
__device__ float  g_v [BN * HID];
__device__ float2 g_rowstats[BN];

// ---------------- f32x2 packed helpers ----------------
__device__ __forceinline__ ull pack2(float x, float y) {
    ull r;
    asm("mov.b64 %0, {%1, %2};" : "=l"(r) : "r"(__float_as_uint(x)), "r"(__float_as_uint(y)));
    return r;
}
__device__ __forceinline__ void unpack2(ull u, float& x, float& y) {
    unsigned a, b;
    asm("mov.b64 {%0, %1}, %2;" : "=r"(a), "=r"(b) : "l"(u));
    x = __uint_as_float(a); y = __uint_as_float(b);
}
__device__ __forceinline__ ull fma2(ull a, ull b, ull c) {
    ull d;
    asm("fma.rn.f32x2 %0, %1, %2, %3;" : "=l"(d) : "l"(a), "l"(b), "l"(c));
    return d;
}
__device__ __forceinline__ ull add2(ull a, ull b) {
    ull d;
    asm("add.rn.f32x2 %0, %1, %2;" : "=l"(d) : "l"(a), "l"(b));
    return d;
}
__device__ __forceinline__ float ex2f(float x) {
    float r;
    asm("ex2.approx.f32 %0, %1;" : "=f"(r) : "f"(x));
    return r;
}

__device__ __forceinline__ float gelu_f(float x) {
    // exact (erf) gelu, matching jax.nn.gelu(approximate=False)
    return 0.5f * x * (1.0f + erff(x * 0.70710678118654752f));
}

// ---------------- per-row order statistics of m_dist ----------------
__global__ void rowstats_kernel(const float* __restrict__ md, float2* __restrict__ rs) {
    int warp = threadIdx.x >> 5, lane = threadIdx.x & 31;
    int row = blockIdx.x * 8 + warp;
    const float* p = md + (size_t)row * NN + lane;
    unsigned mu[64];
    float mn = 1e30f;
#pragma unroll
    for (int i = 0; i < 64; ++i) {
        float x = p[i * 32];
        mn = fminf(mn, x);
        mu[i] = __float_as_uint(x);
    }
#pragma unroll
    for (int off = 16; off; off >>= 1)
        mn = fminf(mn, __shfl_xor_sync(FULLMASK, mn, off));

    unsigned lo = 0u, hi = 0x3F800000u;  // bit patterns of [0,1)
    while (hi - lo > 1u) {
        unsigned mid = (lo + hi) >> 1;
        int c = 0;
#pragma unroll
        for (int i = 0; i < 64; ++i) c += (mu[i] <= mid) ? 1 : 0;
        c = __reduce_add_sync(FULLMASK, c);
        if (c >= KTH) hi = mid; else lo = mid;
    }
    if (lane == 0) rs[row] = make_float2(mn, __uint_as_float(hi));
}

// ---------------- encoder: gelu(inputs @ en_W + en_b), K=3 ----------------
__global__ void enc_kernel(const float* __restrict__ inp, const float* __restrict__ W,
                           const float* __restrict__ bvec, float* __restrict__ out) {
    int token = blockIdx.x, c = threadIdx.x;
    float x0 = inp[token * 3 + 0];
    float x1 = inp[token * 3 + 1];
    float x2 = inp[token * 3 + 2];
    float s = bvec[c];
    s = fmaf(x0, W[c], s);
    s = fmaf(x1, W[HID + c], s);
    s = fmaf(x2, W[2 * HID + c], s);
    out[(size_t)token * HID + c] = gelu_f(s);
}

// ---------------- GEMM body: 32 rows x 64 cols per CTA ----------------
// vproj: W is head-major (H, HID, VD); logical col c maps to
// W[(c>>4)*HID*VD + k*VD + (c&15)] — 4 consecutive cols stay contiguous.
__device__ __forceinline__ void gemm3_body(
    const float* __restrict__ A, const float* __restrict__ W,
    const float* __restrict__ bias, const float* __restrict__ res,
    float* __restrict__ out, int act, int vproj, float* sm)
{
    float* Ws = sm;              // [128][64]
    float* As = sm + 128 * 64;   // [32][128]

    int tid = threadIdx.x, lane = tid & 31, warp = tid >> 5;
    int row0 = blockIdx.x * 32;
    int cbase = blockIdx.y * 64;

    if (vproj) {
#pragma unroll
        for (int idx = tid; idx < 128 * 16; idx += 256) {
            int k = idx >> 4, q = idx & 15;
            int c0 = cbase + q * 4;
            const float* src = W + (size_t)(c0 >> 4) * (HID * VD) + k * VD + (c0 & 15);
            *(float4*)(Ws + k * 64 + q * 4) = *(const float4*)src;
        }
    } else {
#pragma unroll
        for (int idx = tid; idx < 128 * 16; idx += 256) {
            int k = idx >> 4, q = idx & 15;
            *(float4*)(Ws + k * 64 + q * 4) = *(const float4*)(W + (size_t)k * HID + cbase + q * 4);
        }
    }
#pragma unroll
    for (int idx = tid; idx < 32 * 32; idx += 256) {
        int r = idx >> 5, q = idx & 31;
        *(float4*)(As + r * HID + q * 4) = *(const float4*)(A + (size_t)(row0 + r) * HID + q * 4);
    }
    __syncthreads();

    ull acc[4] = {0ull, 0ull, 0ull, 0ull};
    const ull* Wu = (const ull*)Ws;          // [k][32]
    const float* a0 = As + warp * 4 * HID;

#pragma unroll 8
    for (int k = 0; k < HID; ++k) {
        ull wp = Wu[k * 32 + lane];
        float x0 = a0[0 * HID + k];
        float x1 = a0[1 * HID + k];
        float x2 = a0[2 * HID + k];
        float x3 = a0[3 * HID + k];
        acc[0] = fma2(pack2(x0, x0), wp, acc[0]);
        acc[1] = fma2(pack2(x1, x1), wp, acc[1]);
        acc[2] = fma2(pack2(x2, x2), wp, acc[2]);
        acc[3] = fma2(pack2(x3, x3), wp, acc[3]);
    }

    float b0 = 0.f, b1 = 0.f;
    if (bias) {
        float2 bv = *(const float2*)(bias + cbase + 2 * lane);
        b0 = bv.x; b1 = bv.y;
    }
#pragma unroll
    for (int i = 0; i < 4; ++i) {
        int row = row0 + warp * 4 + i;
        float o0, o1;
        unpack2(acc[i], o0, o1);
        o0 += b0; o1 += b1;
        if (res) {
            float2 rv = *(const float2*)(res + (size_t)row * HID + cbase + 2 * lane);
            o0 += rv.x; o1 += rv.y;
        }
        if (act) { o0 = gelu_f(o0); o1 = gelu_f(o1); }
        *(float2*)(out + (size_t)row * HID + cbase + 2 * lane) = make_float2(o0, o1);
    }
}

__global__ void __launch_bounds__(256) gemm3_kernel(
    const float* __restrict__ A, const float* __restrict__ W,
    const float* __restrict__ bias, const float* __restrict__ res,
    float* __restrict__ out, int act)
{
    extern __shared__ float sm[];
    gemm3_body(A, W, bias, res, out, act, 0, sm);
}

// paired GEMM on the same A. z=0: v-proj from head-major Whead (no bias).
// z=1: skip-proj out1 = A@W1 + b1.
__global__ void __launch_bounds__(256) gemm3p_kernel(
    const float* __restrict__ A,
    const float* __restrict__ Whead, float* __restrict__ out0,
    const float* __restrict__ W1, const float* __restrict__ b1,
    float* __restrict__ out1)
{
    extern __shared__ float sm[];
    if (blockIdx.z == 0) gemm3_body(A, Whead, nullptr, nullptr, out0, 0, 1, sm);
    else                 gemm3_body(A, W1,    b1,      nullptr, out1, 0, 0, sm);
}

// ---------------- fused percentile-softmax attention + gelu ----------------
// CTA: 256 threads = 8 warps x 2 rows = 16 rows, one (b,h). v staged in TWO
// 1024-row chunks (72KB, stride 18 -> conflict-free LDS.64) so 3 CTAs fit
// per SM -> 24 warps/SM (vs 16 before): latency hiding is the binding
// resource. Lane <-> j; depth-4 m prefetch ring (~600cyc > 262cyc L2).
// exp once per (i,j); 16 dims as 8 packed f32x2 FMAs.
template <int MASKED>
__global__ void __launch_bounds__(256, 3) attn8_kernel(
    const float* __restrict__ md, const float* __restrict__ v,
    const float* __restrict__ rvec, const float2* __restrict__ rs,
    float* __restrict__ out)
{
    extern __shared__ float vs[];   // [1024][18]
    int b = blockIdx.z, h = blockIdx.y;
    float rr = rvec[h];
    float r2 = rr * rr;
    const float L2E = 1.4426950408889634f;
    float nr2l = -r2 * L2E;

    int tid = threadIdx.x;
    int lane = tid & 31, warp = tid >> 5;
    int i0 = blockIdx.x * 16 + warp * 2;

    float msdl[2], s102[2];
    ull wsum2 = 0ull;
    ull acc[2][8];
#pragma unroll
    for (int g = 0; g < 2; ++g) {
        float2 st = rs[b * NN + i0 + g];
        msdl[g] = (st.x * r2) * L2E;  // st.x*r2 == min_j(sd) exactly (monotone)
        s102[g] = st.y;
#pragma unroll
        for (int d = 0; d < 8; ++d) acc[g][d] = 0ull;
    }

    const float* mrow = md + ((size_t)b * NN + i0) * NN + lane;

    // prime depth-4 m prefetch ring (global step index)
    float mr[2][4];
#pragma unroll
    for (int d = 0; d < 4; ++d) {
        mr[0][d] = mrow[0 * (size_t)NN + 32 * d];
        mr[1][d] = mrow[1 * (size_t)NN + 32 * d];
    }

    for (int c = 0; c < NN / VCHUNK; ++c) {
        __syncthreads();
        // stage v chunk [c*VCHUNK, (c+1)*VCHUNK)
        const float* vg = v + ((size_t)b * NN + c * VCHUNK) * HID + h * VD;
        for (int idx = tid; idx < VCHUNK * 8; idx += 256) {
            int jj = idx >> 3, dd = (idx & 7) << 1;
            float2 val = *(const float2*)(vg + (size_t)jj * HID + dd);
            *(float2*)(vs + jj * 18 + dd) = val;
        }
        __syncthreads();

#pragma unroll 4
        for (int t = 0; t < VCHUNK / 32; ++t) {
            int gt = c * (VCHUNK / 32) + t;
            int slot = gt & 3;

            const ull* vrow = (const ull*)(vs + (lane + 32 * t) * 18);
            ull v0 = vrow[0], v1 = vrow[1], v2 = vrow[2], v3 = vrow[3];
            ull v4 = vrow[4], v5 = vrow[5], v6 = vrow[6], v7 = vrow[7];

            float m0 = mr[0][slot];
            float m1 = mr[1][slot];

            // prefetch m for global step gt+4 (clamped; tail prefetches unused)
            int tp = gt + 4; if (tp > NN / 32 - 1) tp = NN / 32 - 1;
            mr[0][slot] = mrow[0 * (size_t)NN + 32 * tp];
            mr[1][slot] = mrow[1 * (size_t)NN + 32 * tp];

            float e0 = ex2f(fmaf(m0, nr2l, msdl[0]));
            float e1 = ex2f(fmaf(m1, nr2l, msdl[1]));
            float w0 = MASKED ? ((m0 <= s102[0]) ? e0 : 0.f) : e0;
            float w1 = MASKED ? ((m1 <= s102[1]) ? e1 : 0.f) : e1;
            wsum2 = add2(wsum2, pack2(w0, w1));
            ull wp0 = pack2(w0, w0);
            ull wp1 = pack2(w1, w1);

            acc[0][0] = fma2(wp0, v0, acc[0][0]);
            acc[0][1] = fma2(wp0, v1, acc[0][1]);
            acc[0][2] = fma2(wp0, v2, acc[0][2]);
            acc[0][3] = fma2(wp0, v3, acc[0][3]);
            acc[0][4] = fma2(wp0, v4, acc[0][4]);
            acc[0][5] = fma2(wp0, v5, acc[0][5]);
            acc[0][6] = fma2(wp0, v6, acc[0][6]);
            acc[0][7] = fma2(wp0, v7, acc[0][7]);

            acc[1][0] = fma2(wp1, v0, acc[1][0]);
            acc[1][1] = fma2(wp1, v1, acc[1][1]);
            acc[1][2] = fma2(wp1, v2, acc[1][2]);
            acc[1][3] = fma2(wp1, v3, acc[1][3]);
            acc[1][4] = fma2(wp1, v4, acc[1][4]);
            acc[1][5] = fma2(wp1, v5, acc[1][5]);
            acc[1][6] = fma2(wp1, v6, acc[1][6]);
            acc[1][7] = fma2(wp1, v7, acc[1][7]);
        }
    }

    // butterfly reduce across 32 lanes (j slots)
    float wsum[2];
    unpack2(wsum2, wsum[0], wsum[1]);
#pragma unroll
    for (int off = 16; off; off >>= 1) {
#pragma unroll
        for (int g = 0; g < 2; ++g) {
            wsum[g] += __shfl_xor_sync(FULLMASK, wsum[g], off);
#pragma unroll
            for (int d = 0; d < 8; ++d) {
                ull o = __shfl_xor_sync(FULLMASK, acc[g][d], off);
                acc[g][d] = add2(acc[g][d], o);
            }
        }
    }

    if (lane < 2) {
        int g = lane;
        float inv = 1.0f / wsum[g];
        float o[16];
#pragma unroll
        for (int d = 0; d < 8; ++d) unpack2(acc[g][d], o[2 * d], o[2 * d + 1]);
#pragma unroll
        for (int e = 0; e < 16; ++e) o[e] = gelu_f(o[e] * inv);
        float* dst = out + (size_t)(b * NN + i0 + g) * HID + h * VD;
        *(float4*)(dst + 0)  = make_float4(o[0],  o[1],  o[2],  o[3]);
        *(float4*)(dst + 4)  = make_float4(o[4],  o[5],  o[6],  o[7]);
        *(float4*)(dst + 8)  = make_float4(o[8],  o[9],  o[10], o[11]);
        *(float4*)(dst + 12) = make_float4(o[12], o[13], o[14], o[15]);
    }
}

// ---------------- final 128 -> 1 projection ----------------
__global__ void final_kernel(const float* __restrict__ t, const float* __restrict__ W,
                             const float* __restrict__ bvec, float* __restrict__ out) {
    int warp = threadIdx.x >> 5, lane = threadIdx.x & 31;
    int token = blockIdx.x * 8 + warp;
    const float* p = t + (size_t)token * HID;
    float s = 0.f;
#pragma unroll
    for (int i = 0; i < 4; ++i) s = fmaf(p[lane + 32 * i], W[lane + 32 * i], s);
#pragma unroll
    for (int off = 16; off; off >>= 1) s += __shfl_xor_sync(FULLMASK, s, off);
    if (lane == 0) out[token] = s + bvec[0];
}

// ---------------- orchestration ----------------
static float* symf(const void* sym) {
    void* p = nullptr;
    cudaGetSymbolAddress(&p, sym);
    return (float*)p;
}

extern "C" void kernel_launch(void* const* d_in, const int* in_sizes, int n_in,
                              void* d_out, int out_size) {
    const float* md      = (const float*)d_in[0];
    const float* inputs  = (const float*)d_in[1];
    const float* en_W    = (const float*)d_in[2];
    const float* en_b    = (const float*)d_in[3];
    const float* down_r  = (const float*)d_in[4];
    const float* down_w  = (const float*)d_in[5];
    const float* mlp1_W1 = (const float*)d_in[6];
    const float* mlp1_b1 = (const float*)d_in[7];
    const float* mlp1_W2 = (const float*)d_in[8];
    const float* mlp1_b2 = (const float*)d_in[9];
    const float* w1_W    = (const float*)d_in[10];
    const float* w1_b    = (const float*)d_in[11];
    const float* pa_r    = (const float*)d_in[12];
    const float* pa_w    = (const float*)d_in[13];
    const float* blk_W1  = (const float*)d_in[14];
    const float* blk_b1  = (const float*)d_in[15];
    const float* blk_W2  = (const float*)d_in[16];
    const float* blk_b2  = (const float*)d_in[17];
    const float* wi_W    = (const float*)d_in[18];
    const float* wi_b    = (const float*)d_in[19];
    const float* up_r    = (const float*)d_in[20];
    const float* up_w    = (const float*)d_in[21];
    const float* mlp2_W1 = (const float*)d_in[22];
    const float* mlp2_b1 = (const float*)d_in[23];
    const float* mlp2_W2 = (const float*)d_in[24];
    const float* mlp2_b2 = (const float*)d_in[25];
    const float* w2_W    = (const float*)d_in[26];
    const float* w2_b    = (const float*)d_in[27];
    const float* de_W1   = (const float*)d_in[28];
    const float* de_b1   = (const float*)d_in[29];
    const float* de_W2   = (const float*)d_in[30];
    const float* de_b2   = (const float*)d_in[31];
    float* outp = (float*)d_out;

    float*  en = symf(g_en);
    float*  x  = symf(g_x);
    float*  hb = symf(g_h);
    float*  tb = symf(g_t);
    float*  rb = symf(g_r);
    float*  vb = symf(g_v);
    float2* rsp;
    { void* p = nullptr; cudaGetSymbolAddress(&p, g_rowstats); rsp = (float2*)p; }

    cudaFuncSetAttribute(gemm3_kernel,  cudaFuncAttributeMaxDynamicSharedMemorySize, GEMM_SMEM);
    cudaFuncSetAttribute(gemm3p_kernel, cudaFuncAttributeMaxDynamicSharedMemorySize, GEMM_SMEM);
    cudaFuncSetAttribute(attn8_kernel<0>, cudaFuncAttributeMaxDynamicSharedMemorySize, ATTN_SMEM);
    cudaFuncSetAttribute(attn8_kernel<1>, cudaFuncAttributeMaxDynamicSharedMemorySize, ATTN_SMEM);

    dim3 ggrid(BN / 32, 2);
    dim3 pgrid(BN / 32, 2, 2);
    dim3 agrid(NN / 16, HH, BB);

    rowstats_kernel<<<BN / 8, 256>>>(md, rsp);
    enc_kernel<<<BN, HID>>>(inputs, en_W, en_b, en);

    // ---- stage 1 (input en, masked mhpa) ----
    gemm3p_kernel<<<pgrid, 256, GEMM_SMEM>>>(en, down_w, vb, w1_W, w1_b, rb);
    attn8_kernel<1><<<agrid, 256, ATTN_SMEM>>>(md, vb, down_r, rsp, hb);
    gemm3_kernel<<<ggrid, 256, GEMM_SMEM>>>(hb, mlp1_W1, mlp1_b1, nullptr, tb, 1);
    gemm3_kernel<<<ggrid, 256, GEMM_SMEM>>>(tb, mlp1_W2, mlp1_b2, rb, x, 1);

    // ---- 4 unmasked blocks ----
    for (int i = 0; i < 4; ++i) {
        gemm3p_kernel<<<pgrid, 256, GEMM_SMEM>>>(x, pa_w + (size_t)i * HH * HID * VD, vb,
            wi_W + (size_t)i * HID * HID, wi_b + (size_t)i * HID, rb);
        attn8_kernel<0><<<agrid, 256, ATTN_SMEM>>>(md, vb, pa_r + (size_t)i * HH, rsp, hb);
        gemm3_kernel<<<ggrid, 256, GEMM_SMEM>>>(hb, blk_W1 + (size_t)i * HID * HID, blk_b1 + (size_t)i * HID, nullptr, tb, 1);
        gemm3_kernel<<<ggrid, 256, GEMM_SMEM>>>(tb, blk_W2 + (size_t)i * HID * HID, blk_b2 + (size_t)i * HID, rb, x, 1);
    }

    // ---- stage 2 (masked mhpa) ----
    gemm3p_kernel<<<pgrid, 256, GEMM_SMEM>>>(x, up_w, vb, w2_W, w2_b, rb);
    attn8_kernel<1><<<agrid, 256, ATTN_SMEM>>>(md, vb, up_r, rsp, hb);
    gemm3_kernel<<<ggrid, 256, GEMM_SMEM>>>(hb, mlp2_W1, mlp2_b1, nullptr, tb, 1);
    gemm3_kernel<<<ggrid, 256, GEMM_SMEM>>>(tb, mlp2_W2, mlp2_b2, rb, x, 1);   // x = de

    // ---- decoder ----
    gemm3_kernel<<<ggrid, 256, GEMM_SMEM>>>(x, de_W1, de_b1, nullptr, tb, 1);
    final_kernel<<<BN / 8, 256>>>(tb, de_W2, de_b2, outp);
}

// round 10
// speedup vs baseline: 1.3315x; 1.1895x over previous
#include <cuda_runtime.h>
#include <math.h>

#define FULLMASK 0xffffffffu

#define BB   2
#define NN   2048
#define HH   8
#define HID  128
#define VD   16
#define BN   (BB * NN)
// locality=5 -> pos=0.05*2047=102.35 -> need 103rd smallest (0-indexed 102)
#define KTH  103

// GEMM smem: Ws [128][64] f32 (32KB) + As [32][128] f32 (16KB) = 48KB
#define GEMM_SMEM (32768 + 16384)
// Attention smem: half of v (1024 rows x stride-20 f32) = 80KB -> 2 CTAs/SM
#define VCHUNK 1024
#define VSTR   20
#define ATTN_SMEM (VCHUNK * VSTR * 4)

typedef unsigned long long ull;

// ---------------- scratch (device globals; no allocation) ----------------
__device__ float  g_en[BN * HID];
__device__ float  g_x [BN * HID];
__device__ float  g_h [BN * HID];
__device__ float  g_t [BN * HID];
__device__ float  g_r [BN * HID];
__device__ float  g_v [BN * HID];
__device__ float2 g_rowstats[BN];

// ---------------- f32x2 packed helpers ----------------
__device__ __forceinline__ ull pack2(float x, float y) {
    ull r;
    asm("mov.b64 %0, {%1, %2};" : "=l"(r) : "r"(__float_as_uint(x)), "r"(__float_as_uint(y)));
    return r;
}
__device__ __forceinline__ void unpack2(ull u, float& x, float& y) {
    unsigned a, b;
    asm("mov.b64 {%0, %1}, %2;" : "=r"(a), "=r"(b) : "l"(u));
    x = __uint_as_float(a); y = __uint_as_float(b);
}
__device__ __forceinline__ ull fma2(ull a, ull b, ull c) {
    ull d;
    asm("fma.rn.f32x2 %0, %1, %2, %3;" : "=l"(d) : "l"(a), "l"(b), "l"(c));
    return d;
}
__device__ __forceinline__ ull add2(ull a, ull b) {
    ull d;
    asm("add.rn.f32x2 %0, %1, %2;" : "=l"(d) : "l"(a), "l"(b));
    return d;
}
__device__ __forceinline__ float ex2f(float x) {
    float r;
    asm("ex2.approx.f32 %0, %1;" : "=f"(r) : "f"(x));
    return r;
}

__device__ __forceinline__ float gelu_f(float x) {
    // exact (erf) gelu, matching jax.nn.gelu(approximate=False)
    return 0.5f * x * (1.0f + erff(x * 0.70710678118654752f));
}

// ---------------- per-row order statistics of m_dist ----------------
__global__ void rowstats_kernel(const float* __restrict__ md, float2* __restrict__ rs) {
    int warp = threadIdx.x >> 5, lane = threadIdx.x & 31;
    int row = blockIdx.x * 8 + warp;
    const float* p = md + (size_t)row * NN + lane;
    unsigned mu[64];
    float mn = 1e30f;
#pragma unroll
    for (int i = 0; i < 64; ++i) {
        float x = p[i * 32];
        mn = fminf(mn, x);
        mu[i] = __float_as_uint(x);
    }
#pragma unroll
    for (int off = 16; off; off >>= 1)
        mn = fminf(mn, __shfl_xor_sync(FULLMASK, mn, off));

    unsigned lo = 0u, hi = 0x3F800000u;  // bit patterns of [0,1)
    while (hi - lo > 1u) {
        unsigned mid = (lo + hi) >> 1;
        int c = 0;
#pragma unroll
        for (int i = 0; i < 64; ++i) c += (mu[i] <= mid) ? 1 : 0;
        c = __reduce_add_sync(FULLMASK, c);
        if (c >= KTH) hi = mid; else lo = mid;
    }
    if (lane == 0) rs[row] = make_float2(mn, __uint_as_float(hi));
}

// ---------------- encoder: gelu(inputs @ en_W + en_b), K=3 ----------------
__global__ void enc_kernel(const float* __restrict__ inp, const float* __restrict__ W,
                           const float* __restrict__ bvec, float* __restrict__ out) {
    int token = blockIdx.x, c = threadIdx.x;
    float x0 = inp[token * 3 + 0];
    float x1 = inp[token * 3 + 1];
    float x2 = inp[token * 3 + 2];
    float s = bvec[c];
    s = fmaf(x0, W[c], s);
    s = fmaf(x1, W[HID + c], s);
    s = fmaf(x2, W[2 * HID + c], s);
    out[(size_t)token * HID + c] = gelu_f(s);
}

// ---------------- GEMM body: 32 rows x 64 cols per CTA ----------------
// vproj: W is head-major (H, HID, VD); logical col c maps to
// W[(c>>4)*HID*VD + k*VD + (c&15)] — 4 consecutive cols stay contiguous.
__device__ __forceinline__ void gemm3_body(
    const float* __restrict__ A, const float* __restrict__ W,
    const float* __restrict__ bias, const float* __restrict__ res,
    float* __restrict__ out, int act, int vproj, float* sm)
{
    float* Ws = sm;              // [128][64]
    float* As = sm + 128 * 64;   // [32][128]

    int tid = threadIdx.x, lane = tid & 31, warp = tid >> 5;
    int row0 = blockIdx.x * 32;
    int cbase = blockIdx.y * 64;

    if (vproj) {
#pragma unroll
        for (int idx = tid; idx < 128 * 16; idx += 256) {
            int k = idx >> 4, q = idx & 15;
            int c0 = cbase + q * 4;
            const float* src = W + (size_t)(c0 >> 4) * (HID * VD) + k * VD + (c0 & 15);
            *(float4*)(Ws + k * 64 + q * 4) = *(const float4*)src;
        }
    } else {
#pragma unroll
        for (int idx = tid; idx < 128 * 16; idx += 256) {
            int k = idx >> 4, q = idx & 15;
            *(float4*)(Ws + k * 64 + q * 4) = *(const float4*)(W + (size_t)k * HID + cbase + q * 4);
        }
    }
#pragma unroll
    for (int idx = tid; idx < 32 * 32; idx += 256) {
        int r = idx >> 5, q = idx & 31;
        *(float4*)(As + r * HID + q * 4) = *(const float4*)(A + (size_t)(row0 + r) * HID + q * 4);
    }
    __syncthreads();

    ull acc[4] = {0ull, 0ull, 0ull, 0ull};
    const ull* Wu = (const ull*)Ws;          // [k][32]
    const float* a0 = As + warp * 4 * HID;

#pragma unroll 8
    for (int k = 0; k < HID; ++k) {
        ull wp = Wu[k * 32 + lane];
        float x0 = a0[0 * HID + k];
        float x1 = a0[1 * HID + k];
        float x2 = a0[2 * HID + k];
        float x3 = a0[3 * HID + k];
        acc[0] = fma2(pack2(x0, x0), wp, acc[0]);
        acc[1] = fma2(pack2(x1, x1), wp, acc[1]);
        acc[2] = fma2(pack2(x2, x2), wp, acc[2]);
        acc[3] = fma2(pack2(x3, x3), wp, acc[3]);
    }

    float b0 = 0.f, b1 = 0.f;
    if (bias) {
        float2 bv = *(const float2*)(bias + cbase + 2 * lane);
        b0 = bv.x; b1 = bv.y;
    }
#pragma unroll
    for (int i = 0; i < 4; ++i) {
        int row = row0 + warp * 4 + i;
        float o0, o1;
        unpack2(acc[i], o0, o1);
        o0 += b0; o1 += b1;
        if (res) {
            float2 rv = *(const float2*)(res + (size_t)row * HID + cbase + 2 * lane);
            o0 += rv.x; o1 += rv.y;
        }
        if (act) { o0 = gelu_f(o0); o1 = gelu_f(o1); }
        *(float2*)(out + (size_t)row * HID + cbase + 2 * lane) = make_float2(o0, o1);
    }
}

__global__ void __launch_bounds__(256) gemm3_kernel(
    const float* __restrict__ A, const float* __restrict__ W,
    const float* __restrict__ bias, const float* __restrict__ res,
    float* __restrict__ out, int act)
{
    extern __shared__ float sm[];
    gemm3_body(A, W, bias, res, out, act, 0, sm);
}

// paired GEMM on the same A. z=0: v-proj from head-major Whead (no bias).
// z=1: skip-proj out1 = A@W1 + b1.
__global__ void __launch_bounds__(256) gemm3p_kernel(
    const float* __restrict__ A,
    const float* __restrict__ Whead, float* __restrict__ out0,
    const float* __restrict__ W1, const float* __restrict__ b1,
    float* __restrict__ out1)
{
    extern __shared__ float sm[];
    if (blockIdx.z == 0) gemm3_body(A, Whead, nullptr, nullptr, out0, 0, 1, sm);
    else                 gemm3_body(A, W1,    b1,      nullptr, out1, 0, 0, sm);
}

// ---------------- fused percentile-softmax attention + gelu ----------------
// CTA: 256 threads = 8 warps x 4 rows = 32 rows, one (b,h). Lane = (jl 0..15,
// dh 0..1): 16 j-slots, dims split in half across dh -> v LDS is 32B/lane/step
// = 1B/MAC (half of R=2) with only acc[4][4] ull (32 regs, no spill).
// v staged in two 1024-row chunks, stride 20 (aligned LDS.128, conflict-free:
// quarter-warp bank starts {0,20,8,28,16,4,24,12}). 80KB smem -> 2 CTAs/SM.
// Depth-4 m prefetch ring (~600cyc > 262cyc L2). dh-duplicated m loads hit
// identical addresses (no extra L2 sectors); exp duplicated on MUFU only.
template <int MASKED>
__global__ void __launch_bounds__(256, 2) attn9_kernel(
    const float* __restrict__ md, const float* __restrict__ v,
    const float* __restrict__ rvec, const float2* __restrict__ rs,
    float* __restrict__ out)
{
    extern __shared__ float vs[];   // [1024][20]
    int b = blockIdx.z, h = blockIdx.y;
    float rr = rvec[h];
    float r2 = rr * rr;
    const float L2E = 1.4426950408889634f;
    float nr2l = -r2 * L2E;

    int tid = threadIdx.x;
    int lane = tid & 31, warp = tid >> 5;
    int jl = lane & 15, dh = lane >> 4;
    int i0 = blockIdx.x * 32 + warp * 4;

    float msdl[4], s102[4];
    ull wsA = 0ull, wsB = 0ull;
    ull acc[4][4];
#pragma unroll
    for (int g = 0; g < 4; ++g) {
        float2 st = rs[b * NN + i0 + g];
        msdl[g] = (st.x * r2) * L2E;  // st.x*r2 == min_j(sd) exactly (monotone)
        s102[g] = st.y;
#pragma unroll
        for (int d = 0; d < 4; ++d) acc[g][d] = 0ull;
    }

    const float* mrow = md + ((size_t)b * NN + i0) * NN + jl;

    // prime depth-4 m prefetch ring over global 16-wide steps (0..127)
    float mr[4][4];
#pragma unroll
    for (int d = 0; d < 4; ++d)
#pragma unroll
        for (int g = 0; g < 4; ++g) mr[g][d] = mrow[(size_t)g * NN + 16 * d];

    for (int c = 0; c < NN / VCHUNK; ++c) {
        __syncthreads();
        // stage v chunk [c*VCHUNK, (c+1)*VCHUNK)
        const float* vg = v + ((size_t)b * NN + c * VCHUNK) * HID + h * VD;
        for (int idx = tid; idx < VCHUNK * 8; idx += 256) {
            int jj = idx >> 3, dd = (idx & 7) << 1;
            float2 val = *(const float2*)(vg + (size_t)jj * HID + dd);
            *(float2*)(vs + jj * VSTR + dd) = val;
        }
        __syncthreads();

#pragma unroll 4
        for (int t = 0; t < VCHUNK / 16; ++t) {
            int gt = c * (VCHUNK / 16) + t;
            int slot = gt & 3;

            // v half-row for this lane's (j, dh): 8 floats = 2 aligned LDS.128
            const float4* vrow = (const float4*)(vs + (16 * t + jl) * VSTR + dh * 8);
            float4 va = vrow[0], vb4 = vrow[1];
            ull v0 = pack2(va.x, va.y),  v1 = pack2(va.z, va.w);
            ull v2 = pack2(vb4.x, vb4.y), v3 = pack2(vb4.z, vb4.w);

            float m0 = mr[0][slot], m1 = mr[1][slot], m2 = mr[2][slot], m3 = mr[3][slot];

            // prefetch m for global step gt+4 (clamped; tail prefetches unused)
            int tp = gt + 4; if (tp > NN / 16 - 1) tp = NN / 16 - 1;
            mr[0][slot] = mrow[0 * (size_t)NN + 16 * tp];
            mr[1][slot] = mrow[1 * (size_t)NN + 16 * tp];
            mr[2][slot] = mrow[2 * (size_t)NN + 16 * tp];
            mr[3][slot] = mrow[3 * (size_t)NN + 16 * tp];

            float e0 = ex2f(fmaf(m0, nr2l, msdl[0]));
            float e1 = ex2f(fmaf(m1, nr2l, msdl[1]));
            float e2 = ex2f(fmaf(m2, nr2l, msdl[2]));
            float e3 = ex2f(fmaf(m3, nr2l, msdl[3]));
            float w0 = MASKED ? ((m0 <= s102[0]) ? e0 : 0.f) : e0;
            float w1 = MASKED ? ((m1 <= s102[1]) ? e1 : 0.f) : e1;
            float w2 = MASKED ? ((m2 <= s102[2]) ? e2 : 0.f) : e2;
            float w3 = MASKED ? ((m3 <= s102[3]) ? e3 : 0.f) : e3;
            wsA = add2(wsA, pack2(w0, w1));
            wsB = add2(wsB, pack2(w2, w3));
            ull wp0 = pack2(w0, w0);
            ull wp1 = pack2(w1, w1);
            ull wp2 = pack2(w2, w2);
            ull wp3 = pack2(w3, w3);

            acc[0][0] = fma2(wp0, v0, acc[0][0]);  acc[0][1] = fma2(wp0, v1, acc[0][1]);
            acc[0][2] = fma2(wp0, v2, acc[0][2]);  acc[0][3] = fma2(wp0, v3, acc[0][3]);

            acc[1][0] = fma2(wp1, v0, acc[1][0]);  acc[1][1] = fma2(wp1, v1, acc[1][1]);
            acc[1][2] = fma2(wp1, v2, acc[1][2]);  acc[1][3] = fma2(wp1, v3, acc[1][3]);

            acc[2][0] = fma2(wp2, v0, acc[2][0]);  acc[2][1] = fma2(wp2, v1, acc[2][1]);
            acc[2][2] = fma2(wp2, v2, acc[2][2]);  acc[2][3] = fma2(wp2, v3, acc[2][3]);

            acc[3][0] = fma2(wp3, v0, acc[3][0]);  acc[3][1] = fma2(wp3, v1, acc[3][1]);
            acc[3][2] = fma2(wp3, v2, acc[3][2]);  acc[3][3] = fma2(wp3, v3, acc[3][3]);
        }
    }

    // butterfly reduce across the 16 jl slots (xor bits 0..3 stays in dh half)
    float wsum[4];
    unpack2(wsA, wsum[0], wsum[1]);
    unpack2(wsB, wsum[2], wsum[3]);
#pragma unroll
    for (int off = 8; off; off >>= 1) {
#pragma unroll
        for (int g = 0; g < 4; ++g) {
            wsum[g] += __shfl_xor_sync(FULLMASK, wsum[g], off);
#pragma unroll
            for (int d = 0; d < 4; ++d) {
                ull o = __shfl_xor_sync(FULLMASK, acc[g][d], off);
                acc[g][d] = add2(acc[g][d], o);
            }
        }
    }

    if (jl < 4) {
        int g = jl;
        float inv = 1.0f / wsum[g];
        float o[8];
#pragma unroll
        for (int d = 0; d < 4; ++d) unpack2(acc[g][d], o[2 * d], o[2 * d + 1]);
#pragma unroll
        for (int e = 0; e < 8; ++e) o[e] = gelu_f(o[e] * inv);
        float* dst = out + (size_t)(b * NN + i0 + g) * HID + h * VD + dh * 8;
        *(float4*)(dst + 0) = make_float4(o[0], o[1], o[2], o[3]);
        *(float4*)(dst + 4) = make_float4(o[4], o[5], o[6], o[7]);
    }
}

// ---------------- final 128 -> 1 projection ----------------
__global__ void final_kernel(const float* __restrict__ t, const float* __restrict__ W,
                             const float* __restrict__ bvec, float* __restrict__ out) {
    int warp = threadIdx.x >> 5, lane = threadIdx.x & 31;
    int token = blockIdx.x * 8 + warp;
    const float* p = t + (size_t)token * HID;
    float s = 0.f;
#pragma unroll
    for (int i = 0; i < 4; ++i) s = fmaf(p[lane + 32 * i], W[lane + 32 * i], s);
#pragma unroll
    for (int off = 16; off; off >>= 1) s += __shfl_xor_sync(FULLMASK, s, off);
    if (lane == 0) out[token] = s + bvec[0];
}

// ---------------- orchestration ----------------
static float* symf(const void* sym) {
    void* p = nullptr;
    cudaGetSymbolAddress(&p, sym);
    return (float*)p;
}

extern "C" void kernel_launch(void* const* d_in, const int* in_sizes, int n_in,
                              void* d_out, int out_size) {
    const float* md      = (const float*)d_in[0];
    const float* inputs  = (const float*)d_in[1];
    const float* en_W    = (const float*)d_in[2];
    const float* en_b    = (const float*)d_in[3];
    const float* down_r  = (const float*)d_in[4];
    const float* down_w  = (const float*)d_in[5];
    const float* mlp1_W1 = (const float*)d_in[6];
    const float* mlp1_b1 = (const float*)d_in[7];
    const float* mlp1_W2 = (const float*)d_in[8];
    const float* mlp1_b2 = (const float*)d_in[9];
    const float* w1_W    = (const float*)d_in[10];
    const float* w1_b    = (const float*)d_in[11];
    const float* pa_r    = (const float*)d_in[12];
    const float* pa_w    = (const float*)d_in[13];
    const float* blk_W1  = (const float*)d_in[14];
    const float* blk_b1  = (const float*)d_in[15];
    const float* blk_W2  = (const float*)d_in[16];
    const float* blk_b2  = (const float*)d_in[17];
    const float* wi_W    = (const float*)d_in[18];
    const float* wi_b    = (const float*)d_in[19];
    const float* up_r    = (const float*)d_in[20];
    const float* up_w    = (const float*)d_in[21];
    const float* mlp2_W1 = (const float*)d_in[22];
    const float* mlp2_b1 = (const float*)d_in[23];
    const float* mlp2_W2 = (const float*)d_in[24];
    const float* mlp2_b2 = (const float*)d_in[25];
    const float* w2_W    = (const float*)d_in[26];
    const float* w2_b    = (const float*)d_in[27];
    const float* de_W1   = (const float*)d_in[28];
    const float* de_b1   = (const float*)d_in[29];
    const float* de_W2   = (const float*)d_in[30];
    const float* de_b2   = (const float*)d_in[31];
    float* outp = (float*)d_out;

    float*  en = symf(g_en);
    float*  x  = symf(g_x);
    float*  hb = symf(g_h);
    float*  tb = symf(g_t);
    float*  rb = symf(g_r);
    float*  vb = symf(g_v);
    float2* rsp;
    { void* p = nullptr; cudaGetSymbolAddress(&p, g_rowstats); rsp = (float2*)p; }

    cudaFuncSetAttribute(gemm3_kernel,  cudaFuncAttributeMaxDynamicSharedMemorySize, GEMM_SMEM);
    cudaFuncSetAttribute(gemm3p_kernel, cudaFuncAttributeMaxDynamicSharedMemorySize, GEMM_SMEM);
    cudaFuncSetAttribute(attn9_kernel<0>, cudaFuncAttributeMaxDynamicSharedMemorySize, ATTN_SMEM);
    cudaFuncSetAttribute(attn9_kernel<1>, cudaFuncAttributeMaxDynamicSharedMemorySize, ATTN_SMEM);

    dim3 ggrid(BN / 32, 2);
    dim3 pgrid(BN / 32, 2, 2);
    dim3 agrid(NN / 32, HH, BB);

    rowstats_kernel<<<BN / 8, 256>>>(md, rsp);
    enc_kernel<<<BN, HID>>>(inputs, en_W, en_b, en);

    // ---- stage 1 (input en, masked mhpa) ----
    gemm3p_kernel<<<pgrid, 256, GEMM_SMEM>>>(en, down_w, vb, w1_W, w1_b, rb);
    attn9_kernel<1><<<agrid, 256, ATTN_SMEM>>>(md, vb, down_r, rsp, hb);
    gemm3_kernel<<<ggrid, 256, GEMM_SMEM>>>(hb, mlp1_W1, mlp1_b1, nullptr, tb, 1);
    gemm3_kernel<<<ggrid, 256, GEMM_SMEM>>>(tb, mlp1_W2, mlp1_b2, rb, x, 1);

    // ---- 4 unmasked blocks ----
    for (int i = 0; i < 4; ++i) {
        gemm3p_kernel<<<pgrid, 256, GEMM_SMEM>>>(x, pa_w + (size_t)i * HH * HID * VD, vb,
            wi_W + (size_t)i * HID * HID, wi_b + (size_t)i * HID, rb);
        attn9_kernel<0><<<agrid, 256, ATTN_SMEM>>>(md, vb, pa_r + (size_t)i * HH, rsp, hb);
        gemm3_kernel<<<ggrid, 256, GEMM_SMEM>>>(hb, blk_W1 + (size_t)i * HID * HID, blk_b1 + (size_t)i * HID, nullptr, tb, 1);
        gemm3_kernel<<<ggrid, 256, GEMM_SMEM>>>(tb, blk_W2 + (size_t)i * HID * HID, blk_b2 + (size_t)i * HID, rb, x, 1);
    }

    // ---- stage 2 (masked mhpa) ----
    gemm3p_kernel<<<pgrid, 256, GEMM_SMEM>>>(x, up_w, vb, w2_W, w2_b, rb);
    attn9_kernel<1><<<agrid, 256, ATTN_SMEM>>>(md, vb, up_r, rsp, hb);
    gemm3_kernel<<<ggrid, 256, GEMM_SMEM>>>(hb, mlp2_W1, mlp2_b1, nullptr, tb, 1);
    gemm3_kernel<<<ggrid, 256, GEMM_SMEM>>>(tb, mlp2_W2, mlp2_b2, rb, x, 1);   // x = de

    // ---- decoder ----
    gemm3_kernel<<<ggrid, 256, GEMM_SMEM>>>(x, de_W1, de_b1, nullptr, tb, 1);
    final_kernel<<<BN / 8, 256>>>(tb, de_W2, de_b2, outp);
}